// round 3
// baseline (speedup 1.0000x reference)
#include <cuda_runtime.h>

// SpanRepLayer: start / inner-maxpool / end span representations.
// B=2, NS=512, S=1024, H=128, MAX_W=16. Output (B, NS, 3H) fp32.
//
// Inputs (metadata order):
//   d_in[0]: token_reps (B, S, H)  float32
//   d_in[1]: span_ids   (B, NS, 2) int32   [start, end+1]
//   d_in[2]: span_masks (B, NS)    int32 (bool promoted)
// Output: (B, NS, 3H) float32

#define SRL_B  2
#define SRL_NS 512
#define SRL_S  1024
#define SRL_H  128           // 32 float4 per token row
#define SRL_NSPANS (SRL_B * SRL_NS)
#define MAX_INNER 14         // MAX_W=16 -> inner length <= 14
#define NEG_LIMIT -1e9f

__global__ __launch_bounds__(128) void span_rep_kernel(
    const float* __restrict__ token_reps,
    const int2* __restrict__ span_ids,
    const int* __restrict__ span_masks,
    float* __restrict__ out)
{
    const int span = blockIdx.x * 4 + (threadIdx.x >> 5);  // 4 warps/block, 1 span/warp
    const int lane = threadIdx.x & 31;

    float4* o = reinterpret_cast<float4*>(out) + (size_t)span * 96;  // 3H = 96 float4

    if (!span_masks[span]) {
        const float4 z = make_float4(0.f, 0.f, 0.f, 0.f);
        o[lane]      = z;
        o[lane + 32] = z;
        o[lane + 64] = z;
        return;
    }

    const int2 ids  = span_ids[span];
    const int start = ids.x;
    const int end   = ids.y - 1;            // inclusive
    const int inner_len = end - start - 1;  // may be <= 0

    const int b = span >> 9;                // span / SRL_NS
    const float4* __restrict__ base =
        reinterpret_cast<const float4*>(token_reps) + (size_t)b * SRL_S * 32 + lane;

    // Issue ALL loads up front: start, end, and 14 clamped inner rows.
    // Clamping keeps every address valid so no load is predicated off -> max MLP.
    const float4 sr = base[start * 32];
    const float4 er = base[end * 32];

    const int last_i = (inner_len > 0 ? inner_len : 1) - 1;  // clamp index range
    float4 v[MAX_INNER];
    #pragma unroll
    for (int i = 0; i < MAX_INNER; ++i) {
        int ii = i < last_i ? i : last_i;
        v[i] = base[(start + 1 + ii) * 32];
    }

    float4 inner;
    if (inner_len > 0) {
        inner = v[0];
        #pragma unroll
        for (int i = 1; i < MAX_INNER; ++i) {
            if (i < inner_len) {
                inner.x = fmaxf(inner.x, v[i].x);
                inner.y = fmaxf(inner.y, v[i].y);
                inner.z = fmaxf(inner.z, v[i].z);
                inner.w = fmaxf(inner.w, v[i].w);
            }
        }
    } else {
        inner = sr;   // no inner tokens -> start rep
    }

    o[lane]      = sr;
    o[lane + 32] = inner;
    o[lane + 64] = er;
}

extern "C" void kernel_launch(void* const* d_in, const int* in_sizes, int n_in,
                              void* d_out, int out_size)
{
    const float* token_reps = (const float*)d_in[0];
    const int2* span_ids    = (const int2*)d_in[1];
    const int* span_masks   = (const int*)d_in[2];
    float* out              = (float*)d_out;

    span_rep_kernel<<<SRL_NSPANS / 4, 128>>>(token_reps, span_ids, span_masks, out);
}